// round 15
// baseline (speedup 1.0000x reference)
#include <cuda_runtime.h>

#define FFT_M    4096   // complex FFT size (= d/2)
#define NREAL    8192   // sketch / output dim d
#define NTHREADS 256
#define IMG_DIM  2048
#define TXT_DIM  768
#define TWO_PI   6.2831853071795864f

// Padded shared-memory indexing: one extra float2 every 32 float2 (256B).
#define PIDX(i)  ((i) + ((i) >> 5))            // float2 index -> padded float2 index
#define RIDX(i)  ((i) + (((i) >> 6) << 1))     // float  index -> padded float  index
#define PADDED   (FFT_M + (FFT_M >> 5))        // 4224 float2 per buffer

__device__ __forceinline__ float2 cadd(float2 a, float2 b){ return make_float2(a.x+b.x, a.y+b.y); }
__device__ __forceinline__ float2 csub(float2 a, float2 b){ return make_float2(a.x-b.x, a.y-b.y); }
__device__ __forceinline__ float2 cmul(float2 a, float2 b){
    return make_float2(fmaf(a.x, b.x, -a.y*b.y), fmaf(a.x, b.y, a.y*b.x));
}

// 4-point butterfly. DIR=-1 fwd, +1 inv.
template<int DIR>
__device__ __forceinline__ void bfly4(float2 a, float2 b, float2 c, float2 d,
                                      float2& y0, float2& y1, float2& y2, float2& y3) {
    float2 t0 = cadd(a, c), t1 = csub(a, c);
    float2 t2 = cadd(b, d), t3 = csub(b, d);
    float2 jt3 = (DIR < 0) ? make_float2(t3.y, -t3.x) : make_float2(-t3.y, t3.x);
    y0 = cadd(t0, t2); y2 = csub(t0, t2);
    y1 = cadd(t1, jt3); y3 = csub(t1, jt3);
}

// Multiply by W16^{DIR*n}; n is compile-time after unroll (0..9).
template<int DIR>
__device__ __forceinline__ float2 twm16(float2 x, int n) {
    if (n == 0) return x;
    const float C[10] = {1.f, 0.9238795325f, 0.7071067812f, 0.3826834324f, 0.f,
                         -0.3826834324f, -0.7071067812f, -0.9238795325f, -1.f, -0.9238795325f};
    const float S[10] = {0.f, 0.3826834324f, 0.7071067812f, 0.9238795325f, 1.f,
                         0.9238795325f, 0.7071067812f, 0.3826834324f, 0.f, -0.3826834324f};
    return cmul(x, make_float2(C[n], (float)DIR * S[n]));
}

// In-register 16-point DFT (two radix-4 Stockham stages), natural order in/out.
template<int DIR>
__device__ __forceinline__ void dft16(float2 v[16]) {
    float2 t[16];
    #pragma unroll
    for (int j = 0; j < 4; j++) {
        bfly4<DIR>(v[j], v[j+4], v[j+8], v[j+12],
                   t[4*j+0], t[4*j+1], t[4*j+2], t[4*j+3]);
    }
    #pragma unroll
    for (int j = 0; j < 4; j++) {
        float2 a = t[j];
        float2 b = twm16<DIR>(t[j+4],  j);
        float2 c = twm16<DIR>(t[j+8],  2*j);
        float2 d = twm16<DIR>(t[j+12], 3*j);
        bfly4<DIR>(a, b, c, d, v[j], v[j+4], v[j+8], v[j+12]);
    }
}

// Twiddle + 16-pt DFT shared by all stage flavors. m = j & (NS-1).
template<int DIR, int NS>
__device__ __forceinline__ void stage_core(float2 v[16], int m) {
    if (NS > 1) {
        float s, c;
        __sincosf((float)DIR * (TWO_PI / (16.0f * (float)NS)) * (float)m, &s, &c);
        float2 w1 = make_float2(c, s);
        float2 w2 = cmul(w1, w1);
        float2 w3 = cmul(w2, w1);
        float2 w4 = cmul(w2, w2);
        v[1]  = cmul(v[1],  w1);
        v[2]  = cmul(v[2],  w2);
        v[3]  = cmul(v[3],  w3);
        v[4]  = cmul(v[4],  w4);
        v[5]  = cmul(v[5],  cmul(w4, w1));
        v[6]  = cmul(v[6],  cmul(w4, w2));
        v[7]  = cmul(v[7],  cmul(w4, w3));
        float2 w8 = cmul(w4, w4);
        v[8]  = cmul(v[8],  w8);
        v[9]  = cmul(v[9],  cmul(w8, w1));
        v[10] = cmul(v[10], cmul(w8, w2));
        v[11] = cmul(v[11], cmul(w8, w3));
        float2 w12 = cmul(w8, w4);
        v[12] = cmul(v[12], w12);
        v[13] = cmul(v[13], cmul(w12, w1));
        v[14] = cmul(v[14], cmul(w12, w2));
        v[15] = cmul(v[15], cmul(w12, w3));
    }
    dft16<DIR>(v);
}

// Ping-pong radix-16 Stockham stage (no sync inside; caller syncs after).
template<int DIR, int NS>
__device__ __forceinline__ void fft_stage16(const float2* __restrict__ in,
                                            float2* __restrict__ out, int j) {
    float2 v[16];
    #pragma unroll
    for (int a = 0; a < 16; a++) v[a] = in[PIDX(j + 256*a)];
    const int m = j & (NS - 1);
    stage_core<DIR, NS>(v, m);
    const int base = ((j - m) << 4) + m;
    #pragma unroll
    for (int k = 0; k < 16; k++) out[PIDX(base + NS * k)] = v[k];
}

// In-place stage: load all -> compute -> barrier (all loads done) -> store -> barrier.
template<int DIR, int NS>
__device__ __forceinline__ void fft_stage16_ip(float2* __restrict__ buf, int j) {
    float2 v[16];
    #pragma unroll
    for (int a = 0; a < 16; a++) v[a] = buf[PIDX(j + 256*a)];
    const int m = j & (NS - 1);
    stage_core<DIR, NS>(v, m);
    __syncthreads();
    const int base = ((j - m) << 4) + m;
    #pragma unroll
    for (int k = 0; k < 16; k++) buf[PIDX(base + NS * k)] = v[k];
    __syncthreads();
}

__global__ void __launch_bounds__(NTHREADS, 3)
bilinear_fusion_kernel(
    const float* __restrict__ img,  const float* __restrict__ txt,
    const int*   __restrict__ h1,   const int*   __restrict__ h2,
    const float* __restrict__ s1,   const float* __restrict__ s2,
    const float* __restrict__ gamma,const float* __restrict__ beta,
    float* __restrict__ out)
{
    extern __shared__ float2 sm[];
    float2* A = sm;               // sk1 -> Z2 -> ZY -> inv scratch
    float2* B = sm + PADDED;      // FFT scratch -> Z1 -> inv scratch
    __shared__ float rs[8], rq[8];

    const int b   = blockIdx.x;
    const int tid = threadIdx.x;
    float* rA = (float*)A;
    float4* zA = (float4*)A;

    // ---- sketch1: zero A (float4), scatter-add image features ----
    for (int i = tid; i < PADDED/2; i += NTHREADS) zA[i] = make_float4(0.f,0.f,0.f,0.f);
    __syncthreads();
    const float* irow = img + (size_t)b * IMG_DIM;
    for (int i = tid; i < IMG_DIM; i += NTHREADS)
        atomicAdd(&rA[RIDX(h1[i])], irow[i] * s1[i]);
    __syncthreads();

    // ---- forward FFT1 (ping-pong): A->B->A->B, Z1 in B ----
    fft_stage16<-1, 1  >(A, B, tid); __syncthreads();
    fft_stage16<-1, 16 >(B, A, tid); __syncthreads();
    fft_stage16<-1, 256>(A, B, tid); __syncthreads();

    // ---- sketch2: zero A (now free), scatter-add text features ----
    for (int i = tid; i < PADDED/2; i += NTHREADS) zA[i] = make_float4(0.f,0.f,0.f,0.f);
    __syncthreads();
    const float* trow = txt + (size_t)b * TXT_DIM;
    for (int i = tid; i < TXT_DIM; i += NTHREADS)
        atomicAdd(&rA[RIDX(h2[i])], trow[i] * s2[i]);
    __syncthreads();

    // ---- forward FFT2 (in-place on A): Z2 in A ----
    fft_stage16_ip<-1, 1  >(A, tid);
    fft_stage16_ip<-1, 16 >(A, tid);
    fft_stage16_ip<-1, 256>(A, tid);

    // ---- unpack rFFTs, multiply spectra, repack -> ZY in-place into A ----
    // Each {k, M-k} pair is owned by exactly one thread: no barrier needed.
    // Twiddle W_8192^k via recurrence: w(tid+256a) = W^tid * (W^256)^a.
    const float scale = 1.0f / (float)FFT_M;
    {
        float s0, c0;
        __sincosf(-TWO_PI * (float)tid / (float)NREAL, &s0, &c0);
        float2 w = make_float2(c0, s0);
        const float2 cstep = make_float2(0.98078528040323044913f,
                                         -0.19509032201612826785f);  // e^{-2pi i/32}
        #pragma unroll
        for (int a = 0; a < 8; a++) {
            const int k  = tid + 256 * a;                 // 0..2047
            const int mk = (FFT_M - k) & (FFT_M - 1);
            float2 z1k = B[PIDX(k)],  z1m = B[PIDX(mk)];
            float2 z2k = A[PIDX(k)],  z2m = A[PIDX(mk)];

            float2 E1  = make_float2(0.5f*(z1k.x + z1m.x), 0.5f*(z1k.y - z1m.y));
            float2 O1t = make_float2(0.5f*(z1k.x - z1m.x), 0.5f*(z1k.y + z1m.y));
            float2 O1  = make_float2(O1t.y, -O1t.x);      // -i * O1t
            float2 WO1 = cmul(w, O1);
            float2 P1  = cadd(E1, WO1);
            float2 Q1  = csub(E1, WO1);

            float2 E2  = make_float2(0.5f*(z2k.x + z2m.x), 0.5f*(z2k.y - z2m.y));
            float2 O2t = make_float2(0.5f*(z2k.x - z2m.x), 0.5f*(z2k.y + z2m.y));
            float2 O2  = make_float2(O2t.y, -O2t.x);
            float2 WO2 = cmul(w, O2);
            float2 P2  = cadd(E2, WO2);
            float2 Q2  = csub(E2, WO2);

            float2 Yk  = cmul(P1, P2);
            float2 Ymc = cmul(Q1, Q2);                    // conj(Y[M-k])
            float2 G   = make_float2(0.5f*(Yk.x + Ymc.x), 0.5f*(Yk.y + Ymc.y));
            float2 Hm  = make_float2(0.5f*(Yk.x - Ymc.x), 0.5f*(Yk.y - Ymc.y));
            float2 H   = cmul(make_float2(w.x, -w.y), Hm);

            A[PIDX(k)] = make_float2(scale*(G.x - H.y), scale*(G.y + H.x));
            if (k != 0) {
                A[PIDX(mk)] = make_float2(scale*(G.x + H.y), scale*(H.x - G.y));
            }
            w = cmul(w, cstep);
        }
        if (tid == 0) {
            // k = 2048: w = -i, pair is self-conjugate; reduces exactly to
            // ZY[2048] = scale * Z1[2048] * Z2[2048].
            float2 z1k = B[PIDX(2048)];
            float2 z2k = A[PIDX(2048)];
            float2 u = cmul(z1k, z2k);
            A[PIDX(2048)] = make_float2(scale * u.x, scale * u.y);
        }
    }
    __syncthreads();

    // ---- inverse FFT stages 1-2 (ping-pong): A->B->A ----
    fft_stage16<1, 1 >(A, B, tid); __syncthreads();
    fft_stage16<1, 16>(B, A, tid); __syncthreads();

    // ---- fused final stage (NS=256) + LayerNorm + output ----
    // m = tid, base = tid: thread holds y at float2 positions tid + 256k.
    float2 v[16];
    #pragma unroll
    for (int a = 0; a < 16; a++) v[a] = A[PIDX(tid + 256*a)];
    stage_core<1, 256>(v, tid);

    float sum = 0.0f, sq = 0.0f;
    #pragma unroll
    for (int k = 0; k < 16; k++) {
        sum += v[k].x + v[k].y;
        sq = fmaf(v[k].x, v[k].x, sq);
        sq = fmaf(v[k].y, v[k].y, sq);
    }
    #pragma unroll
    for (int o = 16; o; o >>= 1) {
        sum += __shfl_down_sync(0xffffffffu, sum, o);
        sq  += __shfl_down_sync(0xffffffffu, sq,  o);
    }
    const int wid = tid >> 5, lid = tid & 31;
    if (lid == 0) { rs[wid] = sum; rq[wid] = sq; }
    __syncthreads();
    if (wid == 0) {
        sum = (lid < 8) ? rs[lid] : 0.0f;
        sq  = (lid < 8) ? rq[lid] : 0.0f;
        #pragma unroll
        for (int o = 4; o; o >>= 1) {
            sum += __shfl_down_sync(0xffffffffu, sum, o);
            sq  += __shfl_down_sync(0xffffffffu, sq,  o);
        }
        if (lid == 0) { rs[0] = sum; rq[0] = sq; }
    }
    __syncthreads();
    const float mean = rs[0] * (1.0f / (float)NREAL);
    const float var  = rq[0] * (1.0f / (float)NREAL) - mean * mean;
    const float inv  = rsqrtf(var + 1e-5f);

    float2* orow = (float2*)(out + (size_t)b * NREAL);
    const float2* g2 = (const float2*)gamma;
    const float2* b2 = (const float2*)beta;
    #pragma unroll
    for (int k = 0; k < 16; k++) {
        const int n = tid + 256 * k;
        float2 g  = g2[n];
        float2 be = b2[n];
        orow[n] = make_float2(fmaf((v[k].x - mean) * inv, g.x, be.x),
                              fmaf((v[k].y - mean) * inv, g.y, be.y));
    }
}

extern "C" void kernel_launch(void* const* d_in, const int* in_sizes, int n_in,
                              void* d_out, int out_size) {
    const float* img   = (const float*)d_in[0];
    const float* txt   = (const float*)d_in[1];
    const int*   h1    = (const int*)  d_in[2];
    const int*   h2    = (const int*)  d_in[3];
    const float* s1    = (const float*)d_in[4];
    const float* s2    = (const float*)d_in[5];
    const float* gamma = (const float*)d_in[6];
    const float* beta  = (const float*)d_in[7];
    float* out = (float*)d_out;

    const int batch = in_sizes[0] / IMG_DIM;
    const size_t smem = 2 * PADDED * sizeof(float2);   // ~66 KB
    cudaFuncSetAttribute(bilinear_fusion_kernel,
                         cudaFuncAttributeMaxDynamicSharedMemorySize, (int)smem);
    bilinear_fusion_kernel<<<batch, NTHREADS, smem>>>(
        img, txt, h1, h2, s1, s2, gamma, beta, out);
}

// round 17
// speedup vs baseline: 1.0753x; 1.0753x over previous
#include <cuda_runtime.h>

#define FFT_M    4096   // complex FFT size (= d/2)
#define NREAL    8192   // sketch / output dim d
#define NTHREADS 256
#define IMG_DIM  2048
#define TXT_DIM  768
#define TWO_PI   6.2831853071795864f

// Padded shared-memory indexing: one extra float2 every 16 float2 (128B).
// Pad-16 (vs pad-32) makes the NS=1 stage's strided stores conflict-free.
#define PIDX(i)  ((i) + ((i) >> 4))            // float2 index -> padded float2 index
#define RIDX(i)  ((i) + (((i) >> 5) << 1))     // float  index -> padded float  index
#define PADDED   (FFT_M + (FFT_M >> 4))        // 4352 float2 per buffer

__device__ __forceinline__ float2 cadd(float2 a, float2 b){ return make_float2(a.x+b.x, a.y+b.y); }
__device__ __forceinline__ float2 csub(float2 a, float2 b){ return make_float2(a.x-b.x, a.y-b.y); }
__device__ __forceinline__ float2 cmul(float2 a, float2 b){
    return make_float2(fmaf(a.x, b.x, -a.y*b.y), fmaf(a.x, b.y, a.y*b.x));
}

// 4-point butterfly. DIR=-1 fwd, +1 inv.
template<int DIR>
__device__ __forceinline__ void bfly4(float2 a, float2 b, float2 c, float2 d,
                                      float2& y0, float2& y1, float2& y2, float2& y3) {
    float2 t0 = cadd(a, c), t1 = csub(a, c);
    float2 t2 = cadd(b, d), t3 = csub(b, d);
    float2 jt3 = (DIR < 0) ? make_float2(t3.y, -t3.x) : make_float2(-t3.y, t3.x);
    y0 = cadd(t0, t2); y2 = csub(t0, t2);
    y1 = cadd(t1, jt3); y3 = csub(t1, jt3);
}

// Multiply by W16^{DIR*n}; n is compile-time after unroll (0..9).
template<int DIR>
__device__ __forceinline__ float2 twm16(float2 x, int n) {
    if (n == 0) return x;
    const float C[10] = {1.f, 0.9238795325f, 0.7071067812f, 0.3826834324f, 0.f,
                         -0.3826834324f, -0.7071067812f, -0.9238795325f, -1.f, -0.9238795325f};
    const float S[10] = {0.f, 0.3826834324f, 0.7071067812f, 0.9238795325f, 1.f,
                         0.9238795325f, 0.7071067812f, 0.3826834324f, 0.f, -0.3826834324f};
    return cmul(x, make_float2(C[n], (float)DIR * S[n]));
}

// In-register 16-point DFT (two radix-4 Stockham stages), natural order in/out.
template<int DIR>
__device__ __forceinline__ void dft16(float2 v[16]) {
    float2 t[16];
    #pragma unroll
    for (int j = 0; j < 4; j++) {
        bfly4<DIR>(v[j], v[j+4], v[j+8], v[j+12],
                   t[4*j+0], t[4*j+1], t[4*j+2], t[4*j+3]);
    }
    #pragma unroll
    for (int j = 0; j < 4; j++) {
        float2 a = t[j];
        float2 b = twm16<DIR>(t[j+4],  j);
        float2 c = twm16<DIR>(t[j+8],  2*j);
        float2 d = twm16<DIR>(t[j+12], 3*j);
        bfly4<DIR>(a, b, c, d, v[j], v[j+4], v[j+8], v[j+12]);
    }
}

// Twiddle + 16-pt DFT shared by all stage flavors. m = j & (NS-1).
template<int DIR, int NS>
__device__ __forceinline__ void stage_core(float2 v[16], int m) {
    if (NS > 1) {
        float s, c;
        __sincosf((float)DIR * (TWO_PI / (16.0f * (float)NS)) * (float)m, &s, &c);
        float2 w1 = make_float2(c, s);
        float2 w2 = cmul(w1, w1);
        float2 w3 = cmul(w2, w1);
        float2 w4 = cmul(w2, w2);
        v[1]  = cmul(v[1],  w1);
        v[2]  = cmul(v[2],  w2);
        v[3]  = cmul(v[3],  w3);
        v[4]  = cmul(v[4],  w4);
        v[5]  = cmul(v[5],  cmul(w4, w1));
        v[6]  = cmul(v[6],  cmul(w4, w2));
        v[7]  = cmul(v[7],  cmul(w4, w3));
        float2 w8 = cmul(w4, w4);
        v[8]  = cmul(v[8],  w8);
        v[9]  = cmul(v[9],  cmul(w8, w1));
        v[10] = cmul(v[10], cmul(w8, w2));
        v[11] = cmul(v[11], cmul(w8, w3));
        float2 w12 = cmul(w8, w4);
        v[12] = cmul(v[12], w12);
        v[13] = cmul(v[13], cmul(w12, w1));
        v[14] = cmul(v[14], cmul(w12, w2));
        v[15] = cmul(v[15], cmul(w12, w3));
    }
    dft16<DIR>(v);
}

// Ping-pong radix-16 Stockham stage (no sync inside; caller syncs after).
template<int DIR, int NS>
__device__ __forceinline__ void fft_stage16(const float2* __restrict__ in,
                                            float2* __restrict__ out, int j) {
    float2 v[16];
    #pragma unroll
    for (int a = 0; a < 16; a++) v[a] = in[PIDX(j + 256*a)];
    const int m = j & (NS - 1);
    stage_core<DIR, NS>(v, m);
    const int base = ((j - m) << 4) + m;
    #pragma unroll
    for (int k = 0; k < 16; k++) out[PIDX(base + NS * k)] = v[k];
}

// In-place stage. For NS<256: load all -> compute -> barrier -> store -> barrier.
// For NS==256 the store set equals the per-thread load set (base = tid,
// stride 256 -> thread-private indices), so the pre-store barrier is skipped.
template<int DIR, int NS>
__device__ __forceinline__ void fft_stage16_ip(float2* __restrict__ buf, int j) {
    float2 v[16];
    #pragma unroll
    for (int a = 0; a < 16; a++) v[a] = buf[PIDX(j + 256*a)];
    const int m = j & (NS - 1);
    stage_core<DIR, NS>(v, m);
    if (NS != 256) __syncthreads();
    const int base = ((j - m) << 4) + m;
    #pragma unroll
    for (int k = 0; k < 16; k++) buf[PIDX(base + NS * k)] = v[k];
    __syncthreads();
}

__global__ void __launch_bounds__(NTHREADS, 3)
bilinear_fusion_kernel(
    const float* __restrict__ img,  const float* __restrict__ txt,
    const int*   __restrict__ h1,   const int*   __restrict__ h2,
    const float* __restrict__ s1,   const float* __restrict__ s2,
    const float* __restrict__ gamma,const float* __restrict__ beta,
    float* __restrict__ out)
{
    extern __shared__ float2 sm[];
    float2* A = sm;               // sk1 -> Z2 -> ZY -> inv scratch
    float2* B = sm + PADDED;      // FFT scratch -> Z1 -> inv scratch
    __shared__ float rs[8], rq[8];

    const int b   = blockIdx.x;
    const int tid = threadIdx.x;
    float* rA = (float*)A;
    float4* zA = (float4*)A;

    // ---- sketch1: zero A (float4), scatter-add image features ----
    for (int i = tid; i < PADDED/2; i += NTHREADS) zA[i] = make_float4(0.f,0.f,0.f,0.f);
    __syncthreads();
    const float* irow = img + (size_t)b * IMG_DIM;
    for (int i = tid; i < IMG_DIM; i += NTHREADS)
        atomicAdd(&rA[RIDX(h1[i])], irow[i] * s1[i]);
    __syncthreads();

    // ---- forward FFT1 (ping-pong): A->B->A->B, Z1 in B ----
    fft_stage16<-1, 1  >(A, B, tid); __syncthreads();
    fft_stage16<-1, 16 >(B, A, tid); __syncthreads();
    fft_stage16<-1, 256>(A, B, tid); __syncthreads();

    // ---- sketch2: zero A (now free), scatter-add text features ----
    for (int i = tid; i < PADDED/2; i += NTHREADS) zA[i] = make_float4(0.f,0.f,0.f,0.f);
    __syncthreads();
    const float* trow = txt + (size_t)b * TXT_DIM;
    for (int i = tid; i < TXT_DIM; i += NTHREADS)
        atomicAdd(&rA[RIDX(h2[i])], trow[i] * s2[i]);
    __syncthreads();

    // ---- forward FFT2 (in-place on A): Z2 in A ----
    fft_stage16_ip<-1, 1  >(A, tid);
    fft_stage16_ip<-1, 16 >(A, tid);
    fft_stage16_ip<-1, 256>(A, tid);

    // ---- unpack rFFTs, multiply spectra, repack -> ZY in-place into A ----
    // Each {k, M-k} pair is owned by exactly one thread: no barrier needed.
    // Twiddle W_8192^k via recurrence: w(tid+256a) = W^tid * (W^256)^a.
    const float scale = 1.0f / (float)FFT_M;
    {
        float s0, c0;
        __sincosf(-TWO_PI * (float)tid / (float)NREAL, &s0, &c0);
        float2 w = make_float2(c0, s0);
        const float2 cstep = make_float2(0.98078528040323044913f,
                                         -0.19509032201612826785f);  // e^{-2pi i/32}
        #pragma unroll
        for (int a = 0; a < 8; a++) {
            const int k  = tid + 256 * a;                 // 0..2047
            const int mk = (FFT_M - k) & (FFT_M - 1);
            float2 z1k = B[PIDX(k)],  z1m = B[PIDX(mk)];
            float2 z2k = A[PIDX(k)],  z2m = A[PIDX(mk)];

            float2 E1  = make_float2(0.5f*(z1k.x + z1m.x), 0.5f*(z1k.y - z1m.y));
            float2 O1t = make_float2(0.5f*(z1k.x - z1m.x), 0.5f*(z1k.y + z1m.y));
            float2 O1  = make_float2(O1t.y, -O1t.x);      // -i * O1t
            float2 WO1 = cmul(w, O1);
            float2 P1  = cadd(E1, WO1);
            float2 Q1  = csub(E1, WO1);

            float2 E2  = make_float2(0.5f*(z2k.x + z2m.x), 0.5f*(z2k.y - z2m.y));
            float2 O2t = make_float2(0.5f*(z2k.x - z2m.x), 0.5f*(z2k.y + z2m.y));
            float2 O2  = make_float2(O2t.y, -O2t.x);
            float2 WO2 = cmul(w, O2);
            float2 P2  = cadd(E2, WO2);
            float2 Q2  = csub(E2, WO2);

            float2 Yk  = cmul(P1, P2);
            float2 Ymc = cmul(Q1, Q2);                    // conj(Y[M-k])
            float2 G   = make_float2(0.5f*(Yk.x + Ymc.x), 0.5f*(Yk.y + Ymc.y));
            float2 Hm  = make_float2(0.5f*(Yk.x - Ymc.x), 0.5f*(Yk.y - Ymc.y));
            float2 H   = cmul(make_float2(w.x, -w.y), Hm);

            A[PIDX(k)] = make_float2(scale*(G.x - H.y), scale*(G.y + H.x));
            if (k != 0) {
                A[PIDX(mk)] = make_float2(scale*(G.x + H.y), scale*(H.x - G.y));
            }
            w = cmul(w, cstep);
        }
        if (tid == 0) {
            // k = 2048: w = -i, pair is self-conjugate; reduces exactly to
            // ZY[2048] = scale * Z1[2048] * Z2[2048].
            float2 z1k = B[PIDX(2048)];
            float2 z2k = A[PIDX(2048)];
            float2 u = cmul(z1k, z2k);
            A[PIDX(2048)] = make_float2(scale * u.x, scale * u.y);
        }
    }
    __syncthreads();

    // ---- inverse FFT stages 1-2 (ping-pong): A->B->A ----
    fft_stage16<1, 1 >(A, B, tid); __syncthreads();
    fft_stage16<1, 16>(B, A, tid); __syncthreads();

    // ---- fused final stage (NS=256) + LayerNorm + output ----
    // m = tid, base = tid: thread holds y at float2 positions tid + 256k.
    float2 v[16];
    #pragma unroll
    for (int a = 0; a < 16; a++) v[a] = A[PIDX(tid + 256*a)];
    stage_core<1, 256>(v, tid);

    float sum = 0.0f, sq = 0.0f;
    #pragma unroll
    for (int k = 0; k < 16; k++) {
        sum += v[k].x + v[k].y;
        sq = fmaf(v[k].x, v[k].x, sq);
        sq = fmaf(v[k].y, v[k].y, sq);
    }
    #pragma unroll
    for (int o = 16; o; o >>= 1) {
        sum += __shfl_down_sync(0xffffffffu, sum, o);
        sq  += __shfl_down_sync(0xffffffffu, sq,  o);
    }
    const int wid = tid >> 5, lid = tid & 31;
    if (lid == 0) { rs[wid] = sum; rq[wid] = sq; }
    __syncthreads();
    if (wid == 0) {
        sum = (lid < 8) ? rs[lid] : 0.0f;
        sq  = (lid < 8) ? rq[lid] : 0.0f;
        #pragma unroll
        for (int o = 4; o; o >>= 1) {
            sum += __shfl_down_sync(0xffffffffu, sum, o);
            sq  += __shfl_down_sync(0xffffffffu, sq,  o);
        }
        if (lid == 0) { rs[0] = sum; rq[0] = sq; }
    }
    __syncthreads();
    const float mean = rs[0] * (1.0f / (float)NREAL);
    const float var  = rq[0] * (1.0f / (float)NREAL) - mean * mean;
    const float inv  = rsqrtf(var + 1e-5f);

    float2* orow = (float2*)(out + (size_t)b * NREAL);
    const float2* g2 = (const float2*)gamma;
    const float2* b2 = (const float2*)beta;
    #pragma unroll
    for (int k = 0; k < 16; k++) {
        const int n = tid + 256 * k;
        float2 g  = g2[n];
        float2 be = b2[n];
        orow[n] = make_float2(fmaf((v[k].x - mean) * inv, g.x, be.x),
                              fmaf((v[k].y - mean) * inv, g.y, be.y));
    }
}

extern "C" void kernel_launch(void* const* d_in, const int* in_sizes, int n_in,
                              void* d_out, int out_size) {
    const float* img   = (const float*)d_in[0];
    const float* txt   = (const float*)d_in[1];
    const int*   h1    = (const int*)  d_in[2];
    const int*   h2    = (const int*)  d_in[3];
    const float* s1    = (const float*)d_in[4];
    const float* s2    = (const float*)d_in[5];
    const float* gamma = (const float*)d_in[6];
    const float* beta  = (const float*)d_in[7];
    float* out = (float*)d_out;

    const int batch = in_sizes[0] / IMG_DIM;
    const size_t smem = 2 * PADDED * sizeof(float2);   // ~68 KB
    cudaFuncSetAttribute(bilinear_fusion_kernel,
                         cudaFuncAttributeMaxDynamicSharedMemorySize, (int)smem);
    bilinear_fusion_kernel<<<batch, NTHREADS, smem>>>(
        img, txt, h1, h2, s1, s2, gamma, beta, out);
}